// round 8
// baseline (speedup 1.0000x reference)
#include <cuda_runtime.h>
#include <cuda_fp16.h>
#include <cstdint>

#define D_DIM 256
#define N_TOK 32768
#define N_CODE 2048
#define PAD 0.01f

// ---------------- scratch (static device globals) ---------------------------
__device__ __half g_xhi[N_TOK * D_DIM];   // X hi split, A-fragment order
__device__ __half g_ehi[N_CODE * D_DIM];  // E hi split, B-fragment order
__device__ float  g_embed[N_CODE * D_DIM];// E row-major
__device__ float  g_esq[N_CODE];          // ||e||^2 (exact fp32)
__device__ float  g_ehn[N_CODE];          // ||e_hi||
__device__ float  g_eln[N_CODE];          // ||e_lo||
__device__ float  g_xh2[4 * N_TOK];       // per-(chunk,token) ||x_hi||^2 partials
__device__ float  g_xl2[4 * N_TOK];       // per-(chunk,token) ||x_lo||^2 partials
__device__ float  g_pb [N_TOK * 8];       // per-partial best dist
__device__ int    g_pbi[N_TOK * 8];       // per-partial best idx
__device__ float  g_ps1[N_TOK * 8];       // per-partial min s
__device__ int    g_psi[N_TOK * 8];       // its idx
__device__ float  g_ps2[N_TOK * 8];       // second-min s
__device__ int    g_idx[N_TOK];           // final indices
__device__ int    g_flag[N_TOK];          // flagged token list
__device__ int    g_nflag;                // flagged count

// ---------------- helpers ----------------------------------------------------
__device__ __forceinline__ uint32_t smem_u32(const void* p) {
    uint32_t a;
    asm("{ .reg .u64 t; cvta.to.shared.u64 t, %1; cvt.u32.u64 %0, t; }"
        : "=r"(a) : "l"(p));
    return a;
}
__device__ __forceinline__ uint32_t pack2(__half a, __half b) {
    __half2 h2 = __halves2half2(a, b);
    return *reinterpret_cast<uint32_t*>(&h2);
}

#define MBAR_INIT(a, c) asm volatile("mbarrier.init.shared.b64 [%0], %1;" :: "r"(a), "r"((uint32_t)(c)) : "memory")
#define MBAR_EXPECT_TX(a, b) asm volatile("mbarrier.arrive.expect_tx.shared.b64 _, [%0], %1;" :: "r"(a), "r"((uint32_t)(b)) : "memory")
#define MBAR_ARRIVE(a)  asm volatile("mbarrier.arrive.shared.b64 _, [%0];" :: "r"(a) : "memory")

#define MBAR_WAIT(mbar, parity) do {                                          \
    uint32_t _m = (mbar), _ph = (parity), _done;                              \
    asm volatile("{ .reg .pred p; mbarrier.try_wait.parity.acquire.cta.shared::cta.b64 p, [%1], %2; selp.b32 %0, 1, 0, p; }" \
                 : "=r"(_done) : "r"(_m), "r"(_ph) : "memory");               \
    if (!_done) {                                                             \
        asm volatile("{ .reg .pred P1; WL_%=: mbarrier.try_wait.parity.acquire.cta.shared::cta.b64 P1, [%0], %1, 0x989680; @P1 bra.uni WD_%=; bra.uni WL_%=; WD_%=: }" \
                     :: "r"(_m), "r"(_ph) : "memory");                        \
    }                                                                         \
} while (0)

#define BULK_G2S(dst, src, bytes, mbar)                                       \
    asm volatile("cp.async.bulk.shared::cluster.global.mbarrier::complete_tx::bytes [%0], [%1], %2, [%3];" \
                 :: "r"(dst), "l"(src), "r"((uint32_t)(bytes)), "r"(mbar) : "memory")

__device__ __forceinline__ void mma_f16(float* d, const uint32_t* a, const uint32_t* b) {
    asm("mma.sync.aligned.m16n8k16.row.col.f32.f16.f16.f32 "
        "{%0,%1,%2,%3}, {%4,%5,%6,%7}, {%8,%9}, {%0,%1,%2,%3};"
        : "+f"(d[0]), "+f"(d[1]), "+f"(d[2]), "+f"(d[3])
        : "r"(a[0]), "r"(a[1]), "r"(a[2]), "r"(a[3]), "r"(b[0]), "r"(b[1]));
}

// ---------------------------------------------------------------------------
// prep: blocks [0,1024): E prep (2 codes/block) — embed, esq, ||e_hi||,
// ||e_lo||, hi B-fragments. Blocks [1024,2048): X split (hi A-fragments via
// smem stage, coalesced out) + per-(chunk,token) hi/lo norm partials.
// ---------------------------------------------------------------------------
__global__ void __launch_bounds__(256) prep_all_kernel(const float* __restrict__ X,
                                                       const float* __restrict__ embed_sum,
                                                       const float* __restrict__ usage) {
    if (blockIdx.x == 0 && threadIdx.x == 0) g_nflag = 0;

    if (blockIdx.x < N_CODE / 2) {
        int t = threadIdx.x;
        int k = blockIdx.x * 2 + (t >> 7);
        int tl = t & 127;
        __shared__ float wq[8], wh[8], wl[8];

        float u = fmaxf(usage[k], 1e-5f);
        float2 vv = ((const float2*)embed_sum)[k * 128 + tl];
        float v0 = vv.x / u, v1 = vv.y / u;
        ((float2*)g_embed)[k * 128 + tl] = make_float2(v0, v1);

        __half h0 = __float2half_rn(v0);
        __half h1 = __float2half_rn(v1);
        float h0f = __half2float(h0), h1f = __half2float(h1);
        float l0f = v0 - h0f, l1f = v1 - h1f;

        int d = 2 * tl;
        int pass = k >> 7, n_in = k & 127;
        int n_tile = n_in >> 3, ncol = n_in & 7;
        int ch = d >> 6, kk = d & 63, ks = kk >> 4, kc = kk & 15;
        int lane = ncol * 4 + ((kc >> 1) & 3);
        int reg = kc >> 3;
        int hbase = (pass * 4 + ch) * 8192 + ((ks * 16 + n_tile) * 32 + lane) * 4 + reg * 2;
        ((uint32_t*)g_ehi)[hbase >> 1] = pack2(h0, h1);

        float sq = v0 * v0 + v1 * v1;
        float sh = h0f * h0f + h1f * h1f;
        float sl = l0f * l0f + l1f * l1f;
        #pragma unroll
        for (int off = 16; off > 0; off >>= 1) {
            sq += __shfl_down_sync(0xffffffffu, sq, off);
            sh += __shfl_down_sync(0xffffffffu, sh, off);
            sl += __shfl_down_sync(0xffffffffu, sl, off);
        }
        if ((t & 31) == 0) { wq[t >> 5] = sq; wh[t >> 5] = sh; wl[t >> 5] = sl; }
        __syncthreads();
        if (tl == 0) {
            int w0 = (t >> 7) * 4;
            g_esq[k] = wq[w0] + wq[w0 + 1] + wq[w0 + 2] + wq[w0 + 3];
            g_ehn[k] = sqrtf(wh[w0] + wh[w0 + 1] + wh[w0 + 2] + wh[w0 + 3]);
            g_eln[k] = sqrtf(wl[w0] + wl[w0 + 1] + wl[w0 + 2] + wl[w0 + 3]);
        }
    } else {
        __shared__ uint32_t sh_hi[4096];   // 16 KB
        __shared__ float xa_h[128], xa_l[128];
        int tile = blockIdx.x - N_CODE / 2;     // 0..1023
        int m_block = tile >> 2, ch = tile & 3;
        int t = threadIdx.x;
        if (t < 128) { xa_h[t] = 0.f; xa_l[t] = 0.f; }
        __syncthreads();

        #pragma unroll
        for (int it = 0; it < 8; ++it) {
            int i4 = t + it * 256;                 // tile-local float4
            int tok_l = i4 >> 4;
            int dl4 = i4 & 15;
            float4 x = ((const float4*)X)[(size_t)(m_block * 128 + tok_l) * 64 + ch * 16 + dl4];
            float xv[4] = {x.x, x.y, x.z, x.w};
            int m_tile = tok_l >> 4, r = tok_l & 15;
            float hs = 0.f, ls = 0.f;
            #pragma unroll
            for (int j = 0; j < 4; j += 2) {
                __half ha = __float2half_rn(xv[j]);
                __half hb = __float2half_rn(xv[j + 1]);
                float haf = __half2float(ha), hbf = __half2float(hb);
                float laf = xv[j] - haf, lbf = xv[j + 1] - hbf;
                hs += haf * haf + hbf * hbf;
                ls += laf * laf + lbf * lbf;
                int kk = dl4 * 4 + j;
                int ks = kk >> 4, kc = kk & 15;
                int lane = (r & 7) * 4 + ((kc >> 1) & 3);
                int reg = (r >> 3) | ((kc >> 3) << 1);
                int half_loc = ((ks * 8 + m_tile) * 32 + lane) * 8 + reg * 2;
                sh_hi[half_loc >> 1] = pack2(ha, hb);
            }
            atomicAdd(&xa_h[tok_l], hs);
            atomicAdd(&xa_l[tok_l], ls);
        }
        __syncthreads();

        uint4* dh = (uint4*)(((uint32_t*)g_xhi) + tile * 4096);
        const uint4* sh4 = (const uint4*)sh_hi;
        #pragma unroll
        for (int it = 0; it < 4; ++it)
            dh[t + it * 256] = sh4[t + it * 256];

        if (t < 128) {
            int tok = m_block * 128 + t;
            g_xh2[ch * N_TOK + tok] = xa_h[t];
            g_xl2[ch * N_TOK + tok] = xa_l[t];
        }
    }
}

// ---------------------------------------------------------------------------
// Pass 1: hi-only fp16 mma GEMM + filtered argmin over (m-tile 128, q 512).
// Grid 1024, 288 thr (8 compute warps 4m x 2n + 1 producer).
// A hi (64 KB) persistent; B hi rings 3 x 16 KB.
// Tracks best(d~) and top-2 of s = d~ - U per token; writes 8 partials/token.
// SMEM: [0..64) mbars | [1024) esq 2K | [3072) eln 2K | [5120) ehn 2K |
//       [7168) xhn 512 | [7680) xln 512 | [8192) A 64K | [73728) B 3x16K
// ---------------------------------------------------------------------------
#define SMEM_TOTAL 122880
#define A_OFF 8192
#define B_OFF 73728

__global__ void __launch_bounds__(288, 1) argmin_pass1_kernel() {
    extern __shared__ __align__(1024) char smem[];
    uint32_t sb = smem_u32(smem);
    int tid = threadIdx.x, lane = tid & 31, wid = tid >> 5;
    int mtile = blockIdx.x >> 2, q = blockIdx.x & 3;
    int row0 = mtile * 128;

    const uint32_t AF    = sb + 0;
    const uint32_t FB[3] = {sb + 8,  sb + 16, sb + 24};
    const uint32_t EB[3] = {sb + 32, sb + 40, sb + 48};
    float* esq_s = (float*)(smem + 1024);
    float* eln_s = (float*)(smem + 3072);
    float* ehn_s = (float*)(smem + 5120);
    float* xhn_s = (float*)(smem + 7168);
    float* xln_s = (float*)(smem + 7680);

    if (tid == 0) {
        MBAR_INIT(AF, 1);
        #pragma unroll
        for (int s = 0; s < 3; ++s) { MBAR_INIT(FB[s], 1); MBAR_INIT(EB[s], 8); }
    }
    for (int i = tid; i < 512; i += 288) {
        esq_s[i] = g_esq[q * 512 + i];
        eln_s[i] = g_eln[q * 512 + i];
        ehn_s[i] = g_ehn[q * 512 + i];
    }
    if (tid < 128) {
        int tok = row0 + tid;
        xhn_s[tid] = sqrtf(g_xh2[tok] + g_xh2[N_TOK + tok] +
                           g_xh2[2 * N_TOK + tok] + g_xh2[3 * N_TOK + tok]);
        xln_s[tid] = sqrtf(g_xl2[tok] + g_xl2[N_TOK + tok] +
                           g_xl2[2 * N_TOK + tok] + g_xl2[3 * N_TOK + tok]);
    }
    __syncthreads();

    if (wid == 8) {
        if (lane == 0) {
            MBAR_EXPECT_TX(AF, 65536);
            #pragma unroll
            for (int ch = 0; ch < 4; ++ch)
                BULK_G2S(sb + A_OFF + ch * 16384,
                         &g_xhi[(mtile * 4 + ch) * 8192], 16384, AF);
            #pragma unroll 1
            for (int g = 0; g < 16; ++g) {
                int s = g % 3;
                if (g >= 3) MBAR_WAIT(EB[s], ((g / 3) + 1) & 1);
                int pass = g >> 2, ch = g & 3;
                MBAR_EXPECT_TX(FB[s], 16384);
                BULK_G2S(sb + B_OFF + s * 16384,
                         &g_ehi[((q * 4 + pass) * 4 + ch) * 8192], 16384, FB[s]);
            }
        }
    } else {
        int warp_m = wid & 3, warp_n = wid >> 2;
        int t4 = lane & 3, g4 = lane >> 2;

        // per token-slot (mt, h): best(d~), top-2 of s
        float b[2][2], s1[2][2], s2[2][2];
        int   bi[2][2], si[2][2];
        float xh[2][2], xl[2][2];
        #pragma unroll
        for (int mt = 0; mt < 2; ++mt)
            #pragma unroll
            for (int h = 0; h < 2; ++h) {
                b[mt][h] = 3.4e38f; bi[mt][h] = 0;
                s1[mt][h] = 3.4e38f; si[mt][h] = 0; s2[mt][h] = 3.4e38f;
                int tok_l = warp_m * 32 + mt * 16 + g4 + 8 * h;
                xh[mt][h] = xhn_s[tok_l];
                xl[mt][h] = xln_s[tok_l];
            }

        MBAR_WAIT(AF, 0);

        #pragma unroll 1
        for (int pass = 0; pass < 4; ++pass) {
            float acc[2][8][4];
            #pragma unroll
            for (int mt = 0; mt < 2; ++mt)
                #pragma unroll
                for (int nt = 0; nt < 8; ++nt)
                    #pragma unroll
                    for (int j = 0; j < 4; ++j) acc[mt][nt][j] = 0.f;

            #pragma unroll 1
            for (int ch = 0; ch < 4; ++ch) {
                int g = pass * 4 + ch;
                int s = g % 3;
                MBAR_WAIT(FB[s], (g / 3) & 1);

                const char* Ah = smem + A_OFF + ch * 16384;
                const char* Bh = smem + B_OFF + s * 16384;

                #pragma unroll
                for (int ks = 0; ks < 4; ++ks) {
                    uint32_t ah[2][4];
                    #pragma unroll
                    for (int mt = 0; mt < 2; ++mt) {
                        int off = ((ks * 8 + warp_m * 2 + mt) * 32 + lane) * 16;
                        *(uint4*)ah[mt] = *(const uint4*)(Ah + off);
                    }
                    uint32_t bh[8][2];
                    #pragma unroll
                    for (int nt = 0; nt < 8; ++nt) {
                        int off = ((ks * 16 + warp_n * 8 + nt) * 32 + lane) * 8;
                        *(uint2*)bh[nt] = *(const uint2*)(Bh + off);
                    }
                    #pragma unroll
                    for (int mt = 0; mt < 2; ++mt)
                        #pragma unroll
                        for (int nt = 0; nt < 8; ++nt)
                            mma_f16(acc[mt][nt], ah[mt], bh[nt]);
                }
                if (lane == 0) MBAR_ARRIVE(EB[s]);
            }

            // epilogue: d~ = esq - 2*dot ; s = d~ - U(token, code)
            #pragma unroll
            for (int nt = 0; nt < 8; ++nt) {
                int cl = pass * 128 + warp_n * 64 + nt * 8 + 2 * t4;
                float e0 = esq_s[cl], e1 = esq_s[cl + 1];
                float ln0 = eln_s[cl], ln1 = eln_s[cl + 1];
                float hn0 = ehn_s[cl], hn1 = ehn_s[cl + 1];
                int c0 = q * 512 + cl, c1 = c0 + 1;
                #pragma unroll
                for (int mt = 0; mt < 2; ++mt)
                    #pragma unroll
                    for (int h = 0; h < 2; ++h) {
                        float d0 = fmaf(-2.f, acc[mt][nt][2 * h + 0], e0);
                        float d1 = fmaf(-2.f, acc[mt][nt][2 * h + 1], e1);
                        float u0 = 2.f * fmaf(xh[mt][h], ln0, xl[mt][h] * hn0) + PAD;
                        float u1 = 2.f * fmaf(xh[mt][h], ln1, xl[mt][h] * hn1) + PAD;
                        if (d0 < b[mt][h]) { b[mt][h] = d0; bi[mt][h] = c0; }
                        if (d1 < b[mt][h]) { b[mt][h] = d1; bi[mt][h] = c1; }
                        float sv0 = d0 - u0, sv1 = d1 - u1;
                        if (sv0 < s1[mt][h]) { s2[mt][h] = s1[mt][h]; s1[mt][h] = sv0; si[mt][h] = c0; }
                        else if (sv0 < s2[mt][h]) s2[mt][h] = sv0;
                        if (sv1 < s1[mt][h]) { s2[mt][h] = s1[mt][h]; s1[mt][h] = sv1; si[mt][h] = c1; }
                        else if (sv1 < s2[mt][h]) s2[mt][h] = sv1;
                    }
            }
        }

        // width-4 shuffle merge, write partials
        #pragma unroll
        for (int mt = 0; mt < 2; ++mt)
            #pragma unroll
            for (int h = 0; h < 2; ++h) {
                float bb = b[mt][h]; int bbi = bi[mt][h];
                float t1 = s1[mt][h]; int ti = si[mt][h]; float t2 = s2[mt][h];
                #pragma unroll
                for (int off = 2; off > 0; off >>= 1) {
                    float ob  = __shfl_down_sync(0xffffffffu, bb, off, 4);
                    int   obi = __shfl_down_sync(0xffffffffu, bbi, off, 4);
                    float o1  = __shfl_down_sync(0xffffffffu, t1, off, 4);
                    int   oi  = __shfl_down_sync(0xffffffffu, ti, off, 4);
                    float o2  = __shfl_down_sync(0xffffffffu, t2, off, 4);
                    if (ob < bb || (ob == bb && obi < bbi)) { bb = ob; bbi = obi; }
                    if (o1 < t1) { t2 = fminf(t1, o2); t1 = o1; ti = oi; }
                    else         { t2 = fminf(t2, o1); }
                }
                if (t4 == 0) {
                    int tok = row0 + warp_m * 32 + mt * 16 + g4 + 8 * h;
                    int part = tok * 8 + q * 2 + warp_n;
                    g_pb[part] = bb;  g_pbi[part] = bbi;
                    g_ps1[part] = t1; g_psi[part] = ti; g_ps2[part] = t2;
                }
            }
    }
}

// ---------------------------------------------------------------------------
// merge: per token fold 8 partials; certify or flag for fallback.
// ---------------------------------------------------------------------------
__global__ void __launch_bounds__(256) merge_kernel() {
    int tok = blockIdx.x * 256 + threadIdx.x;
    float b = 3.4e38f; int bi = 0;
    float s1 = 3.4e38f; int si = 0; float s2 = 3.4e38f;
    #pragma unroll
    for (int p = 0; p < 8; ++p) {
        float ob = g_pb[tok * 8 + p]; int obi = g_pbi[tok * 8 + p];
        if (ob < b || (ob == b && obi < bi)) { b = ob; bi = obi; }
        float o1 = g_ps1[tok * 8 + p]; int oi = g_psi[tok * 8 + p];
        float o2 = g_ps2[tok * 8 + p];
        if (o1 < s1) { s2 = fminf(s1, o2); s1 = o1; si = oi; }
        else         { s2 = fminf(s2, o1); }
    }
    float xh = sqrtf(g_xh2[tok] + g_xh2[N_TOK + tok] +
                     g_xh2[2 * N_TOK + tok] + g_xh2[3 * N_TOK + tok]);
    float xl = sqrtf(g_xl2[tok] + g_xl2[N_TOK + tok] +
                     g_xl2[2 * N_TOK + tok] + g_xl2[3 * N_TOK + tok]);
    float U1 = 2.f * fmaf(xh, g_eln[bi], xl * g_ehn[bi]) + PAD;
    float comp = (si == bi) ? s2 : s1;
    g_idx[tok] = bi;
    if (comp <= b + U1) {
        int p = atomicAdd(&g_nflag, 1);
        g_flag[p] = tok;
    }
}

// ---------------------------------------------------------------------------
// fallback: exact fp32 rescan for flagged tokens. 16 tokens/CTA; smem-tiled.
// ---------------------------------------------------------------------------
__global__ void __launch_bounds__(256) fallback_kernel(const float* __restrict__ X) {
    __shared__ float xs[16 * 260];
    __shared__ float es[16 * 260];
    __shared__ int toks[16];
    int tid = threadIdx.x;
    int nf = g_nflag;

    for (int base = blockIdx.x * 16; base < nf; base += gridDim.x * 16) {
        __syncthreads();
        int nt_ = nf - base; if (nt_ > 16) nt_ = 16;
        if (tid < 16) toks[tid] = g_flag[base + (tid < nt_ ? tid : nt_ - 1)];
        __syncthreads();
        for (int i = tid; i < 16 * 64; i += 256) {
            int t = i >> 6, d4 = i & 63;
            float4 v = ((const float4*)X)[(size_t)toks[t] * 64 + d4];
            *(float4*)&xs[t * 260 + d4 * 4] = v;
        }

        int ts = tid >> 4, cs = tid & 15;
        float best = 3.4e38f; int besti = 0;

        #pragma unroll 1
        for (int c0 = 0; c0 < N_CODE; c0 += 16) {
            __syncthreads();
            for (int i = tid; i < 16 * 64; i += 256) {
                int c = i >> 6, d4 = i & 63;
                float4 v = ((const float4*)g_embed)[(size_t)(c0 + c) * 64 + d4];
                *(float4*)&es[c * 260 + d4 * 4] = v;
            }
            __syncthreads();
            float dot = 0.f;
            #pragma unroll 8
            for (int d4 = 0; d4 < 64; ++d4) {
                float4 xv = *(const float4*)&xs[ts * 260 + d4 * 4];
                float4 ev = *(const float4*)&es[cs * 260 + d4 * 4];
                dot = fmaf(xv.x, ev.x, dot);
                dot = fmaf(xv.y, ev.y, dot);
                dot = fmaf(xv.z, ev.z, dot);
                dot = fmaf(xv.w, ev.w, dot);
            }
            float dist = fmaf(-2.f, dot, g_esq[c0 + cs]);
            if (dist < best) { best = dist; besti = c0 + cs; }
        }
        // reduce across 16 c-lanes sharing a token (half-warp)
        #pragma unroll
        for (int off = 8; off > 0; off >>= 1) {
            float ob = __shfl_down_sync(0xffffffffu, best, off, 16);
            int obi = __shfl_down_sync(0xffffffffu, besti, off, 16);
            if (ob < best || (ob == best && obi < besti)) { best = ob; besti = obi; }
        }
        if ((tid & 15) == 0) g_idx[toks[ts]] = besti;
    }
}

// ---------------------------------------------------------------------------
__global__ void __launch_bounds__(256) gather_kernel(float* __restrict__ out, int N) {
    int i = blockIdx.x * 256 + threadIdx.x;
    int tok = i >> 6, c4 = i & 63;
    int idx = g_idx[tok];
    float4 v = ((const float4*)g_embed)[(size_t)idx * 64 + c4];
    ((float4*)out)[i] = v;
    if (c4 == 0) out[(size_t)N * D_DIM + tok] = (float)idx;
}

// ---------------------------------------------------------------------------
extern "C" void kernel_launch(void* const* d_in, const int* in_sizes, int n_in,
                              void* d_out, int out_size) {
    const float* X  = (const float*)d_in[0];
    const float* ES = (const float*)d_in[1];
    const float* U  = (const float*)d_in[2];
    float* out = (float*)d_out;
    (void)n_in; (void)out_size;
    int N = in_sizes[0] / D_DIM;   // 32768

    cudaFuncSetAttribute(argmin_pass1_kernel,
                         cudaFuncAttributeMaxDynamicSharedMemorySize, SMEM_TOTAL);

    prep_all_kernel<<<N_CODE / 2 + (N / 128) * 4, 256>>>(X, ES, U);
    argmin_pass1_kernel<<<(N / 128) * 4, 288, SMEM_TOTAL>>>();
    merge_kernel<<<N / 256, 256>>>();
    fallback_kernel<<<256, 256>>>(X);
    gather_kernel<<<(N * 64) / 256, 256>>>(out, N);
}

// round 9
// speedup vs baseline: 1.5185x; 1.5185x over previous
#include <cuda_runtime.h>
#include <cuda_fp16.h>
#include <cstdint>

#define D_DIM 256
#define N_TOK 32768
#define N_CODE 2048
#define CAP 40

// ---------------- scratch (static device globals) ---------------------------
__device__ __half g_xhi[N_TOK * D_DIM];   // X hi split, A-fragment order
__device__ __half g_ehi[N_CODE * D_DIM];  // E hi split, B-fragment order
__device__ float  g_embed[N_CODE * D_DIM];// E row-major
__device__ float  g_esq[N_CODE];          // ||e||^2
__device__ float  g_eln[N_CODE];          // ||e_lo||
__device__ float  g_xh2[4 * N_TOK];       // per-(chunk,token) ||x_hi||^2 partials
__device__ float  g_xl2[4 * N_TOK];       // per-(chunk,token) ||x_lo||^2 partials
__device__ int    g_cnt[N_TOK];           // candidate counts
__device__ int    g_cand[N_TOK * CAP];    // candidate code ids
__device__ int    g_idx[N_TOK];           // final indices

// ---------------- helpers ----------------------------------------------------
__device__ __forceinline__ uint32_t smem_u32(const void* p) {
    uint32_t a;
    asm("{ .reg .u64 t; cvta.to.shared.u64 t, %1; cvt.u32.u64 %0, t; }"
        : "=r"(a) : "l"(p));
    return a;
}
__device__ __forceinline__ uint32_t pack2(__half a, __half b) {
    __half2 h2 = __halves2half2(a, b);
    return *reinterpret_cast<uint32_t*>(&h2);
}

#define MBAR_INIT(a, c) asm volatile("mbarrier.init.shared.b64 [%0], %1;" :: "r"(a), "r"((uint32_t)(c)) : "memory")
#define MBAR_EXPECT_TX(a, b) asm volatile("mbarrier.arrive.expect_tx.shared.b64 _, [%0], %1;" :: "r"(a), "r"((uint32_t)(b)) : "memory")
#define MBAR_ARRIVE(a)  asm volatile("mbarrier.arrive.shared.b64 _, [%0];" :: "r"(a) : "memory")

#define MBAR_WAIT(mbar, parity) do {                                          \
    uint32_t _m = (mbar), _ph = (parity), _done;                              \
    asm volatile("{ .reg .pred p; mbarrier.try_wait.parity.acquire.cta.shared::cta.b64 p, [%1], %2; selp.b32 %0, 1, 0, p; }" \
                 : "=r"(_done) : "r"(_m), "r"(_ph) : "memory");               \
    if (!_done) {                                                             \
        asm volatile("{ .reg .pred P1; WL_%=: mbarrier.try_wait.parity.acquire.cta.shared::cta.b64 P1, [%0], %1, 0x989680; @P1 bra.uni WD_%=; bra.uni WL_%=; WD_%=: }" \
                     :: "r"(_m), "r"(_ph) : "memory");                        \
    }                                                                         \
} while (0)

#define BULK_G2S(dst, src, bytes, mbar)                                       \
    asm volatile("cp.async.bulk.shared::cluster.global.mbarrier::complete_tx::bytes [%0], [%1], %2, [%3];" \
                 :: "r"(dst), "l"(src), "r"((uint32_t)(bytes)), "r"(mbar) : "memory")

__device__ __forceinline__ void mma_f16(float* d, const uint32_t* a, const uint32_t* b) {
    asm("mma.sync.aligned.m16n8k16.row.col.f32.f16.f16.f32 "
        "{%0,%1,%2,%3}, {%4,%5,%6,%7}, {%8,%9}, {%0,%1,%2,%3};"
        : "+f"(d[0]), "+f"(d[1]), "+f"(d[2]), "+f"(d[3])
        : "r"(a[0]), "r"(a[1]), "r"(a[2]), "r"(a[3]), "r"(b[0]), "r"(b[1]));
}

// ---------------------------------------------------------------------------
// prep: blocks [0,1024): E prep (2 codes/block) — embed, esq, ||e_lo||, hi
// B-fragments. Blocks [1024,2048): X split hi A-fragments (smem-staged,
// coalesced out) + per-(chunk,token) hi/lo norm partials + g_cnt zeroing.
// ---------------------------------------------------------------------------
__global__ void __launch_bounds__(256) prep_all_kernel(const float* __restrict__ X,
                                                       const float* __restrict__ embed_sum,
                                                       const float* __restrict__ usage) {
    if (blockIdx.x < N_CODE / 2) {
        int t = threadIdx.x;
        int k = blockIdx.x * 2 + (t >> 7);
        int tl = t & 127;
        __shared__ float wq[8], wl[8];

        float u = fmaxf(usage[k], 1e-5f);
        float2 vv = ((const float2*)embed_sum)[k * 128 + tl];
        float v0 = vv.x / u, v1 = vv.y / u;
        ((float2*)g_embed)[k * 128 + tl] = make_float2(v0, v1);

        __half h0 = __float2half_rn(v0);
        __half h1 = __float2half_rn(v1);
        float l0f = v0 - __half2float(h0), l1f = v1 - __half2float(h1);

        int d = 2 * tl;
        int pass = k >> 7, n_in = k & 127;
        int n_tile = n_in >> 3, ncol = n_in & 7;
        int ch = d >> 6, kk = d & 63, ks = kk >> 4, kc = kk & 15;
        int lane = ncol * 4 + ((kc >> 1) & 3);
        int reg = kc >> 3;
        int hbase = (pass * 4 + ch) * 8192 + ((ks * 16 + n_tile) * 32 + lane) * 4 + reg * 2;
        ((uint32_t*)g_ehi)[hbase >> 1] = pack2(h0, h1);

        float sq = v0 * v0 + v1 * v1;
        float sl = l0f * l0f + l1f * l1f;
        #pragma unroll
        for (int off = 16; off > 0; off >>= 1) {
            sq += __shfl_down_sync(0xffffffffu, sq, off);
            sl += __shfl_down_sync(0xffffffffu, sl, off);
        }
        if ((t & 31) == 0) { wq[t >> 5] = sq; wl[t >> 5] = sl; }
        __syncthreads();
        if (tl == 0) {
            int w0 = (t >> 7) * 4;
            g_esq[k] = wq[w0] + wq[w0 + 1] + wq[w0 + 2] + wq[w0 + 3];
            g_eln[k] = sqrtf(wl[w0] + wl[w0 + 1] + wl[w0 + 2] + wl[w0 + 3]);
        }
    } else {
        __shared__ uint32_t sh_hi[4096];   // 16 KB
        __shared__ float xa_h[128], xa_l[128];
        int tile = blockIdx.x - N_CODE / 2;     // 0..1023
        int m_block = tile >> 2, ch = tile & 3;
        int t = threadIdx.x;
        if (t < 128) { xa_h[t] = 0.f; xa_l[t] = 0.f; }
        if (t < 32) g_cnt[tile * 32 + t] = 0;
        __syncthreads();

        #pragma unroll
        for (int it = 0; it < 8; ++it) {
            int i4 = t + it * 256;
            int tok_l = i4 >> 4;
            int dl4 = i4 & 15;
            float4 x = ((const float4*)X)[(size_t)(m_block * 128 + tok_l) * 64 + ch * 16 + dl4];
            float xv[4] = {x.x, x.y, x.z, x.w};
            int m_tile = tok_l >> 4, r = tok_l & 15;
            float hs = 0.f, ls = 0.f;
            #pragma unroll
            for (int j = 0; j < 4; j += 2) {
                __half ha = __float2half_rn(xv[j]);
                __half hb = __float2half_rn(xv[j + 1]);
                float haf = __half2float(ha), hbf = __half2float(hb);
                float laf = xv[j] - haf, lbf = xv[j + 1] - hbf;
                hs += haf * haf + hbf * hbf;
                ls += laf * laf + lbf * lbf;
                int kk = dl4 * 4 + j;
                int ks = kk >> 4, kc = kk & 15;
                int lane = (r & 7) * 4 + ((kc >> 1) & 3);
                int reg = (r >> 3) | ((kc >> 3) << 1);
                int half_loc = ((ks * 8 + m_tile) * 32 + lane) * 8 + reg * 2;
                sh_hi[half_loc >> 1] = pack2(ha, hb);
            }
            atomicAdd(&xa_h[tok_l], hs);
            atomicAdd(&xa_l[tok_l], ls);
        }
        __syncthreads();

        uint4* dh = (uint4*)(((uint32_t*)g_xhi) + tile * 4096);
        const uint4* sh4 = (const uint4*)sh_hi;
        #pragma unroll
        for (int it = 0; it < 4; ++it)
            dh[t + it * 256] = sh4[t + it * 256];

        if (t < 128) {
            int tok = m_block * 128 + t;
            g_xh2[ch * N_TOK + tok] = xa_h[t];
            g_xl2[ch * N_TOK + tok] = xa_l[t];
        }
    }
}

// ---------------------------------------------------------------------------
// Stage A: hi-only fp16 mma GEMM; per token collect candidate codes with
// d~ - U <= B_running (running min of d~ + U, always >= global B  =>
// certified superset containing the true argmin, with strict exclusion).
// Grid 1024 = 256 m-tiles x 4 quarters; 288 thr = 8 compute + 1 producer.
// ---------------------------------------------------------------------------
#define SMEM_TOTAL 124928
#define A_OFF 10240
#define B_OFF 75776

__global__ void __launch_bounds__(288, 1) stageA_kernel() {
    extern __shared__ __align__(1024) char smem[];
    uint32_t sb = smem_u32(smem);
    int tid = threadIdx.x, lane = tid & 31, wid = tid >> 5;
    int mtile = blockIdx.x >> 2, q = blockIdx.x & 3;
    int row0 = mtile * 128;

    const uint32_t AF    = sb + 0;
    const uint32_t FB[3] = {sb + 8,  sb + 16, sb + 24};
    const uint32_t EB[3] = {sb + 32, sb + 40, sb + 48};
    float* esq_s = (float*)(smem + 1024);   // [512]
    float* A_s   = (float*)(smem + 3072);   // 2*||e_lo||
    float* B_s   = (float*)(smem + 5120);   // 2*||e||
    float* C_s   = (float*)(smem + 7168);   // constant pad per code
    float* xhn_s = (float*)(smem + 9216);   // [128]
    float* xln_s = (float*)(smem + 9728);   // [128]

    if (tid == 0) {
        MBAR_INIT(AF, 1);
        #pragma unroll
        for (int s = 0; s < 3; ++s) { MBAR_INIT(FB[s], 1); MBAR_INIT(EB[s], 8); }
    }
    for (int i = tid; i < 512; i += 288) {
        float e2 = g_esq[q * 512 + i];
        float en = sqrtf(e2);
        esq_s[i] = e2;
        A_s[i] = 2.f * g_eln[q * 512 + i];
        B_s[i] = 2.f * en;
        // pads: MMA fp32 accum (~3e-4*en*…), epilogue fp32 rounding at |d|~esq
        C_s[i] = 2e-3f + 2e-3f * en + 1e-6f * e2;
    }
    if (tid < 128) {
        int tok = row0 + tid;
        xhn_s[tid] = sqrtf(g_xh2[tok] + g_xh2[N_TOK + tok] +
                           g_xh2[2 * N_TOK + tok] + g_xh2[3 * N_TOK + tok]);
        xln_s[tid] = sqrtf(g_xl2[tok] + g_xl2[N_TOK + tok] +
                           g_xl2[2 * N_TOK + tok] + g_xl2[3 * N_TOK + tok]);
    }
    __syncthreads();

    if (wid == 8) {
        if (lane == 0) {
            MBAR_EXPECT_TX(AF, 65536);
            #pragma unroll
            for (int ch = 0; ch < 4; ++ch)
                BULK_G2S(sb + A_OFF + ch * 16384,
                         &g_xhi[(mtile * 4 + ch) * 8192], 16384, AF);
            #pragma unroll 1
            for (int g = 0; g < 16; ++g) {
                int s = g % 3;
                if (g >= 3) MBAR_WAIT(EB[s], ((g / 3) + 1) & 1);
                int pass = g >> 2, ch = g & 3;
                MBAR_EXPECT_TX(FB[s], 16384);
                BULK_G2S(sb + B_OFF + s * 16384,
                         &g_ehi[((q * 4 + pass) * 4 + ch) * 8192], 16384, FB[s]);
            }
        }
    } else {
        int warp_m = wid & 3, warp_n = wid >> 2;
        int t4 = lane & 3, g4 = lane >> 2;

        float xh[2][2], xl[2][2], Brun[2][2];
        #pragma unroll
        for (int mt = 0; mt < 2; ++mt)
            #pragma unroll
            for (int h = 0; h < 2; ++h) {
                int tok_l = warp_m * 32 + mt * 16 + g4 + 8 * h;
                xh[mt][h] = xhn_s[tok_l];
                xl[mt][h] = xln_s[tok_l];
                Brun[mt][h] = 3.4e38f;
            }

        MBAR_WAIT(AF, 0);

        #pragma unroll 1
        for (int pass = 0; pass < 4; ++pass) {
            float acc[2][8][4];
            #pragma unroll
            for (int mt = 0; mt < 2; ++mt)
                #pragma unroll
                for (int nt = 0; nt < 8; ++nt)
                    #pragma unroll
                    for (int j = 0; j < 4; ++j) acc[mt][nt][j] = 0.f;

            #pragma unroll 1
            for (int ch = 0; ch < 4; ++ch) {
                int g = pass * 4 + ch;
                int s = g % 3;
                MBAR_WAIT(FB[s], (g / 3) & 1);
                const char* Ah = smem + A_OFF + ch * 16384;
                const char* Bh = smem + B_OFF + s * 16384;
                #pragma unroll
                for (int ks = 0; ks < 4; ++ks) {
                    uint32_t ah[2][4];
                    #pragma unroll
                    for (int mt = 0; mt < 2; ++mt) {
                        int off = ((ks * 8 + warp_m * 2 + mt) * 32 + lane) * 16;
                        *(uint4*)ah[mt] = *(const uint4*)(Ah + off);
                    }
                    uint32_t bh[8][2];
                    #pragma unroll
                    for (int nt = 0; nt < 8; ++nt) {
                        int off = ((ks * 16 + warp_n * 8 + nt) * 32 + lane) * 8;
                        *(uint2*)bh[nt] = *(const uint2*)(Bh + off);
                    }
                    #pragma unroll
                    for (int mt = 0; mt < 2; ++mt)
                        #pragma unroll
                        for (int nt = 0; nt < 8; ++nt)
                            mma_f16(acc[mt][nt], ah[mt], bh[nt]);
                }
                if (lane == 0) MBAR_ARRIVE(EB[s]);
            }

            // ---- epilogue phase 1: update B_running = min(d~ + U) ----------
            float m1[2][2];
            #pragma unroll
            for (int mt = 0; mt < 2; ++mt)
                #pragma unroll
                for (int h = 0; h < 2; ++h) m1[mt][h] = 3.4e38f;

            #pragma unroll
            for (int nt = 0; nt < 8; ++nt) {
                int cl = pass * 128 + warp_n * 64 + nt * 8 + 2 * t4;
                float e0 = esq_s[cl], e1 = esq_s[cl + 1];
                float A0 = A_s[cl], A1 = A_s[cl + 1];
                float B0 = B_s[cl], B1 = B_s[cl + 1];
                float C0 = C_s[cl], C1 = C_s[cl + 1];
                #pragma unroll
                for (int mt = 0; mt < 2; ++mt)
                    #pragma unroll
                    for (int h = 0; h < 2; ++h) {
                        float u0 = fmaf(xh[mt][h], A0, fmaf(xl[mt][h], B0, C0));
                        float u1 = fmaf(xh[mt][h], A1, fmaf(xl[mt][h], B1, C1));
                        float d0 = fmaf(-2.f, acc[mt][nt][2 * h + 0], e0);
                        float d1 = fmaf(-2.f, acc[mt][nt][2 * h + 1], e1);
                        m1[mt][h] = fminf(m1[mt][h], fminf(d0 + u0, d1 + u1));
                    }
            }
            #pragma unroll
            for (int mt = 0; mt < 2; ++mt)
                #pragma unroll
                for (int h = 0; h < 2; ++h) {
                    float m = m1[mt][h];
                    m = fminf(m, __shfl_xor_sync(0xffffffffu, m, 1, 4));
                    m = fminf(m, __shfl_xor_sync(0xffffffffu, m, 2, 4));
                    Brun[mt][h] = fminf(Brun[mt][h], m);
                }

            // ---- epilogue phase 2: collect candidates ----------------------
            #pragma unroll
            for (int nt = 0; nt < 8; ++nt) {
                int cl = pass * 128 + warp_n * 64 + nt * 8 + 2 * t4;
                float e0 = esq_s[cl], e1 = esq_s[cl + 1];
                float A0 = A_s[cl], A1 = A_s[cl + 1];
                float B0 = B_s[cl], B1 = B_s[cl + 1];
                float C0 = C_s[cl], C1 = C_s[cl + 1];
                int c0 = q * 512 + cl;
                #pragma unroll
                for (int mt = 0; mt < 2; ++mt)
                    #pragma unroll
                    for (int h = 0; h < 2; ++h) {
                        float u0 = fmaf(xh[mt][h], A0, fmaf(xl[mt][h], B0, C0));
                        float u1 = fmaf(xh[mt][h], A1, fmaf(xl[mt][h], B1, C1));
                        float d0 = fmaf(-2.f, acc[mt][nt][2 * h + 0], e0);
                        float d1 = fmaf(-2.f, acc[mt][nt][2 * h + 1], e1);
                        int tok = row0 + warp_m * 32 + mt * 16 + g4 + 8 * h;
                        if (d0 - u0 <= Brun[mt][h]) {
                            int pos = atomicAdd(&g_cnt[tok], 1);
                            if (pos < CAP) g_cand[tok * CAP + pos] = c0;
                        }
                        if (d1 - u1 <= Brun[mt][h]) {
                            int pos = atomicAdd(&g_cnt[tok], 1);
                            if (pos < CAP) g_cand[tok * CAP + pos] = c0 + 1;
                        }
                    }
            }
        }
    }
}

// ---------------------------------------------------------------------------
// eval: exact fp32 distance for each candidate; warp per token. On overflow
// (>CAP candidates) the warp scans all codes. Deterministic (min, tie->idx).
// ---------------------------------------------------------------------------
__global__ void __launch_bounds__(256) eval_kernel(const float* __restrict__ X) {
    int wid = threadIdx.x >> 5, lane = threadIdx.x & 31;
    int tok = blockIdx.x * 8 + wid;

    const float4* xr = (const float4*)(X + (size_t)tok * 256 + lane * 8);
    float4 x0 = xr[0], x1 = xr[1];
    int cnt = g_cnt[tok];
    float best = 3.4e38f;
    int bi = 0x7fffffff;

    int limit = (cnt <= CAP) ? cnt : N_CODE;
    #pragma unroll 1
    for (int c = 0; c < limit; ++c) {
        int code = (cnt <= CAP) ? g_cand[tok * CAP + c] : c;
        const float4* er = (const float4*)(g_embed + (size_t)code * 256 + lane * 8);
        float4 e0 = er[0], e1 = er[1];
        float dot = x0.x * e0.x + x0.y * e0.y + x0.z * e0.z + x0.w * e0.w
                  + x1.x * e1.x + x1.y * e1.y + x1.z * e1.z + x1.w * e1.w;
        #pragma unroll
        for (int off = 16; off > 0; off >>= 1)
            dot += __shfl_xor_sync(0xffffffffu, dot, off);
        float dist = fmaf(-2.f, dot, g_esq[code]);
        if (dist < best || (dist == best && code < bi)) { best = dist; bi = code; }
    }
    if (lane == 0) g_idx[tok] = bi;
}

// ---------------------------------------------------------------------------
__global__ void __launch_bounds__(256) gather_kernel(float* __restrict__ out, int N) {
    int i = blockIdx.x * 256 + threadIdx.x;
    int tok = i >> 6, c4 = i & 63;
    int idx = g_idx[tok];
    float4 v = ((const float4*)g_embed)[(size_t)idx * 64 + c4];
    ((float4*)out)[i] = v;
    if (c4 == 0) out[(size_t)N * D_DIM + tok] = (float)idx;
}

// ---------------------------------------------------------------------------
extern "C" void kernel_launch(void* const* d_in, const int* in_sizes, int n_in,
                              void* d_out, int out_size) {
    const float* X  = (const float*)d_in[0];
    const float* ES = (const float*)d_in[1];
    const float* U  = (const float*)d_in[2];
    float* out = (float*)d_out;
    (void)n_in; (void)out_size;
    int N = in_sizes[0] / D_DIM;   // 32768

    cudaFuncSetAttribute(stageA_kernel,
                         cudaFuncAttributeMaxDynamicSharedMemorySize, SMEM_TOTAL);

    prep_all_kernel<<<N_CODE / 2 + (N / 128) * 4, 256>>>(X, ES, U);
    stageA_kernel<<<(N / 128) * 4, 288, SMEM_TOTAL>>>();
    eval_kernel<<<N / 8, 256>>>(X);
    gather_kernel<<<(N * 64) / 256, 256>>>(out, N);
}